// round 2
// baseline (speedup 1.0000x reference)
#include <cuda_runtime.h>
#include <cuda_bf16.h>
#include <math.h>

#define BB    2
#define SS    2048
#define MEMN  512
#define KN    2560
#define HN    16
#define DH    64
#define DM    1024
#define LPOS  (2*KN-1)        /* 5119 */
#define SCALE_F 0.03125f      /* 1/sqrt(1024) */
#define EPSF  1e-5f
#define NEG_BIG (-1e30f)

// ------------------- device scratch (no allocation allowed) -------------------
__device__ float g_cn [BB*KN*DM];        // LN([memory; hidden])  (b, t, dm)
__device__ float g_q  [BB*HN*SS*DH];     // (b,h,s,d)
__device__ float g_k  [BB*HN*KN*DH];     // (b,h,t,d)
__device__ float g_v  [BB*HN*KN*DH];     // (b,h,t,d)
__device__ float g_att[BB*SS*HN*DH];     // (b,s, h*64+d)

// =========================== LayerNorm ===========================
__global__ void __launch_bounds__(256) ln_kernel(const float* __restrict__ hidden,
                                                 const float* __restrict__ memory,
                                                 const float* __restrict__ gamma,
                                                 const float* __restrict__ beta) {
    __shared__ float red[8];
    __shared__ float s_mu, s_inv;
    const int row = blockIdx.x;                 // 0 .. B*K-1
    const int b = row / KN, t = row % KN;
    const float* src = (t < MEMN) ? (memory + ((size_t)b*MEMN + t)*DM)
                                  : (hidden + ((size_t)b*SS + (t - MEMN))*DM);
    const int tid = threadIdx.x;
    float4 x = *(const float4*)(src + tid*4);

    float s = x.x + x.y + x.z + x.w;
    #pragma unroll
    for (int o = 16; o; o >>= 1) s += __shfl_xor_sync(0xffffffffu, s, o);
    if ((tid & 31) == 0) red[tid >> 5] = s;
    __syncthreads();
    if (tid == 0) {
        float tot = 0.f;
        #pragma unroll
        for (int i = 0; i < 8; i++) tot += red[i];
        s_mu = tot * (1.0f / DM);
    }
    __syncthreads();
    const float mu = s_mu;
    float d0 = x.x - mu, d1 = x.y - mu, d2 = x.z - mu, d3 = x.w - mu;
    float vs = d0*d0 + d1*d1 + d2*d2 + d3*d3;
    #pragma unroll
    for (int o = 16; o; o >>= 1) vs += __shfl_xor_sync(0xffffffffu, vs, o);
    if ((tid & 31) == 0) red[tid >> 5] = vs;
    __syncthreads();
    if (tid == 0) {
        float tot = 0.f;
        #pragma unroll
        for (int i = 0; i < 8; i++) tot += red[i];
        s_inv = rsqrtf(tot * (1.0f / DM) + EPSF);
    }
    __syncthreads();
    const float inv = s_inv;
    float4 g = *(const float4*)(gamma + tid*4);
    float4 be = *(const float4*)(beta + tid*4);
    float4 y;
    y.x = d0 * inv * g.x + be.x;
    y.y = d1 * inv * g.y + be.y;
    y.z = d2 * inv * g.z + be.z;
    y.w = d3 * inv * g.w + be.w;
    *(float4*)(g_cn + (size_t)row*DM + tid*4) = y;
}

// =========================== QKV projection GEMM ===========================
// C(rows x 1024) = cn_rows @ W, written as dst[((b*H + h)*rowsPB + r)*64 + d]
__global__ void __launch_bounds__(256) gemm_qkv_kernel(const float* __restrict__ W,
                                                       float* __restrict__ dst,
                                                       int rowsPB, int rowOffset) {
    __shared__ float Ast[16][68];
    __shared__ float Ws [16][68];
    const int tid = threadIdx.x;
    const int tx = tid & 15, ty = tid >> 4;
    const int r0g = blockIdx.x * 64;
    const int b   = r0g / rowsPB;
    const int rin = r0g % rowsPB;
    const float* Abase = g_cn + (size_t)(b*KN + rowOffset + rin) * DM;
    const int n0 = blockIdx.y * 64;

    const int a_m  = tid >> 2;   // 0..63
    const int a_c4 = tid & 3;    // 0..3
    const int w_k  = tid >> 4;   // 0..15
    const int w_c4 = tid & 15;   // 0..15

    float acc[4][4] = {};
    for (int k0 = 0; k0 < DM; k0 += 16) {
        float4 av = *(const float4*)(Abase + (size_t)a_m*DM + k0 + a_c4*4);
        float4 wv = *(const float4*)(W + (size_t)(k0 + w_k)*DM + n0 + w_c4*4);
        __syncthreads();
        Ast[a_c4*4+0][a_m] = av.x;
        Ast[a_c4*4+1][a_m] = av.y;
        Ast[a_c4*4+2][a_m] = av.z;
        Ast[a_c4*4+3][a_m] = av.w;
        *(float4*)&Ws[w_k][w_c4*4] = wv;
        __syncthreads();
        #pragma unroll
        for (int kk = 0; kk < 16; ++kk) {
            float4 a4 = *(const float4*)&Ast[kk][ty*4];
            float4 b4 = *(const float4*)&Ws[kk][tx*4];
            float a[4] = {a4.x, a4.y, a4.z, a4.w};
            float bb[4] = {b4.x, b4.y, b4.z, b4.w};
            #pragma unroll
            for (int i = 0; i < 4; i++)
                #pragma unroll
                for (int j = 0; j < 4; j++)
                    acc[i][j] = fmaf(a[i], bb[j], acc[i][j]);
        }
    }
    // blockIdx.y == head (BN=64 == DH)
    float* dbase = dst + ((size_t)(b*HN + blockIdx.y)*rowsPB + rin) * DH;
    #pragma unroll
    for (int i = 0; i < 4; i++) {
        int m = ty*4 + i;
        *(float4*)(dbase + (size_t)m*DH + tx*4) =
            make_float4(acc[i][0], acc[i][1], acc[i][2], acc[i][3]);
    }
}

// =========================== Output GEMM + residual ===========================
__global__ void __launch_bounds__(256) gemm_out_kernel(const float* __restrict__ Wo,
                                                       float* __restrict__ out) {
    __shared__ float Ast[16][68];
    __shared__ float Ws [16][68];
    const int tid = threadIdx.x;
    const int tx = tid & 15, ty = tid >> 4;
    const int r0g = blockIdx.x * 64;           // rows of (B*S)
    const int b   = r0g / SS;
    const int rin = r0g % SS;
    const float* Abase = g_att + (size_t)r0g * DM;
    const int n0 = blockIdx.y * 64;

    const int a_m  = tid >> 2;
    const int a_c4 = tid & 3;
    const int w_k  = tid >> 4;
    const int w_c4 = tid & 15;

    float acc[4][4] = {};
    for (int k0 = 0; k0 < DM; k0 += 16) {
        float4 av = *(const float4*)(Abase + (size_t)a_m*DM + k0 + a_c4*4);
        float4 wv = *(const float4*)(Wo + (size_t)(k0 + w_k)*DM + n0 + w_c4*4);
        __syncthreads();
        Ast[a_c4*4+0][a_m] = av.x;
        Ast[a_c4*4+1][a_m] = av.y;
        Ast[a_c4*4+2][a_m] = av.z;
        Ast[a_c4*4+3][a_m] = av.w;
        *(float4*)&Ws[w_k][w_c4*4] = wv;
        __syncthreads();
        #pragma unroll
        for (int kk = 0; kk < 16; ++kk) {
            float4 a4 = *(const float4*)&Ast[kk][ty*4];
            float4 b4 = *(const float4*)&Ws[kk][tx*4];
            float a[4] = {a4.x, a4.y, a4.z, a4.w};
            float bb[4] = {b4.x, b4.y, b4.z, b4.w};
            #pragma unroll
            for (int i = 0; i < 4; i++)
                #pragma unroll
                for (int j = 0; j < 4; j++)
                    acc[i][j] = fmaf(a[i], bb[j], acc[i][j]);
        }
    }
    #pragma unroll
    for (int i = 0; i < 4; i++) {
        int m = ty*4 + i;
        const float4 hn = *(const float4*)(g_cn + (size_t)(b*KN + MEMN + rin + m)*DM + n0 + tx*4);
        float4 y = make_float4(acc[i][0] + hn.x, acc[i][1] + hn.y,
                               acc[i][2] + hn.z, acc[i][3] + hn.w);
        *(float4*)(out + (size_t)(r0g + m)*DM + n0 + tx*4) = y;
    }
}

// =========================== Fused flash attention ===========================
// grid: (S/64, H, B); block 256. Per key tile: S = Q K^T + diag-gather(Q P^T),
// online softmax, O += P V. Mask is analytic (triangular on the last tile only).
#define QT_STRIDE 68
#define PT_STRIDE 132
__global__ void __launch_bounds__(256, 2) flash_kernel(const float* __restrict__ pos) {
    extern __shared__ float sm[];
    float* sQt = sm;                         // [d][si]  64 x 68
    float* sKt = sQt + 64*QT_STRIDE;         // [d][ji]  64 x 68
    float* sV  = sKt + 64*QT_STRIDE;         // [ji][d]  64 x 68
    float* sPt = sV  + 64*QT_STRIDE;         // [d][r]   64 x 132  (r in 0..127)
    float* sS  = sPt + 64*PT_STRIDE;         // [si][ji] 64 x 68

    const int b = blockIdx.z, h = blockIdx.y, qt = blockIdx.x;
    const int s0 = qt * 64;
    const int tid = threadIdx.x;
    const int tx = tid & 15, ty = tid >> 4;
    const int wb0 = 60 + 4*(tx - ty);        // 0..120

    const float* qbase = g_q + ((size_t)(b*HN + h)*SS + s0) * DH;
    const float* kbase = g_k + ((size_t)(b*HN + h)*KN) * DH;
    const float* vbase = g_v + ((size_t)(b*HN + h)*KN) * DH;
    const float* pbase = pos + (size_t)b * LPOS * DH;

    // load Q transposed: sQt[d][si]
    #pragma unroll
    for (int l = 0; l < 4; l++) {
        int f  = l*256 + tid;
        int r  = (f >> 2) & 63;
        int c4 = (f & 3) | ((f >> 8) << 2);
        float4 v = *(const float4*)(qbase + (size_t)r*DH + c4*4);
        sQt[(c4*4+0)*QT_STRIDE + r] = v.x;
        sQt[(c4*4+1)*QT_STRIDE + r] = v.y;
        sQt[(c4*4+2)*QT_STRIDE + r] = v.z;
        sQt[(c4*4+3)*QT_STRIDE + r] = v.w;
    }

    float mrow[4], lrow[4], O[4][4];
    #pragma unroll
    for (int i = 0; i < 4; i++) {
        mrow[i] = NEG_BIG; lrow[i] = 0.f;
        #pragma unroll
        for (int j = 0; j < 4; j++) O[i][j] = 0.f;
    }

    const int ntile = qt + 9;
    for (int jt = 0; jt < ntile; jt++) {
        const int j0 = jt * 64;
        __syncthreads();   // previous PV / Q-load complete before overwrite

        // K transposed
        #pragma unroll
        for (int l = 0; l < 4; l++) {
            int f  = l*256 + tid;
            int r  = (f >> 2) & 63;
            int c4 = (f & 3) | ((f >> 8) << 2);
            float4 v = *(const float4*)(kbase + (size_t)(j0 + r)*DH + c4*4);
            sKt[(c4*4+0)*QT_STRIDE + r] = v.x;
            sKt[(c4*4+1)*QT_STRIDE + r] = v.y;
            sKt[(c4*4+2)*QT_STRIDE + r] = v.z;
            sKt[(c4*4+3)*QT_STRIDE + r] = v.w;
        }
        // V natural
        #pragma unroll
        for (int l = 0; l < 4; l++) {
            int f  = l*256 + tid;
            int r  = f >> 4;          // 0..63
            int c4 = f & 15;
            float4 v = *(const float4*)(vbase + (size_t)(j0 + r)*DH + c4*4);
            *(float4*)&sV[r*QT_STRIDE + c4*4] = v;
        }
        // P window transposed: rows wb..wb+127, sPt[d][r]
        const int wb = 1984 + j0 - s0;        // always in [0, 2496]
        #pragma unroll
        for (int l = 0; l < 8; l++) {
            int f  = l*256 + tid;
            int r  = (f >> 2) & 127;
            int c4 = (f & 3) | ((f >> 9) << 2);
            float4 v = *(const float4*)(pbase + (size_t)(wb + r)*DH + c4*4);
            sPt[(c4*4+0)*PT_STRIDE + r] = v.x;
            sPt[(c4*4+1)*PT_STRIDE + r] = v.y;
            sPt[(c4*4+2)*PT_STRIDE + r] = v.z;
            sPt[(c4*4+3)*PT_STRIDE + r] = v.w;
        }
        __syncthreads();

        // scores: S[i][j] = sum_d q[i]*(k[j] + p[63 + (tx4+j) - (ty4+i) - wb0])
        float S[4][4] = {};
        #pragma unroll 4
        for (int d = 0; d < 64; ++d) {
            float4 q4 = *(const float4*)&sQt[d*QT_STRIDE + ty*4];
            float4 k4 = *(const float4*)&sKt[d*QT_STRIDE + tx*4];
            float4 pa = *(const float4*)&sPt[d*PT_STRIDE + wb0];
            float4 pb = *(const float4*)&sPt[d*PT_STRIDE + wb0 + 4];
            float q[4] = {q4.x, q4.y, q4.z, q4.w};
            float k[4] = {k4.x, k4.y, k4.z, k4.w};
            float p[8] = {pa.x, pa.y, pa.z, pa.w, pb.x, pb.y, pb.z, pb.w};
            #pragma unroll
            for (int i = 0; i < 4; i++)
                #pragma unroll
                for (int j = 0; j < 4; j++)
                    S[i][j] = fmaf(q[i], k[j] + p[3 + j - i], S[i][j]);
        }

        const bool lastmask = (jt == qt + 8);
        #pragma unroll
        for (int i = 0; i < 4; i++)
            #pragma unroll
            for (int j = 0; j < 4; j++) {
                float v = S[i][j] * SCALE_F;
                if (lastmask && (4*tx + j > 4*ty + i)) v = NEG_BIG;
                S[i][j] = v;
            }

        // online softmax update (row reductions over 16 tx lanes)
        #pragma unroll
        for (int i = 0; i < 4; i++) {
            float mt = fmaxf(fmaxf(S[i][0], S[i][1]), fmaxf(S[i][2], S[i][3]));
            #pragma unroll
            for (int o = 8; o; o >>= 1) mt = fmaxf(mt, __shfl_xor_sync(0xffffffffu, mt, o));
            float mn = fmaxf(mrow[i], mt);
            float corr = __expf(mrow[i] - mn);
            mrow[i] = mn;
            float rs = 0.f;
            #pragma unroll
            for (int j = 0; j < 4; j++) {
                float p = __expf(S[i][j] - mn);
                rs += p;
                sS[(ty*4 + i)*QT_STRIDE + tx*4 + j] = p;
            }
            #pragma unroll
            for (int o = 8; o; o >>= 1) rs += __shfl_xor_sync(0xffffffffu, rs, o);
            lrow[i] = lrow[i]*corr + rs;
            #pragma unroll
            for (int j = 0; j < 4; j++) O[i][j] *= corr;
        }
        __syncthreads();

        // O += P @ V
        #pragma unroll 4
        for (int ji = 0; ji < 64; ++ji) {
            float4 v4 = *(const float4*)&sV[ji*QT_STRIDE + tx*4];
            float vv[4] = {v4.x, v4.y, v4.z, v4.w};
            float p0 = sS[(ty*4+0)*QT_STRIDE + ji];
            float p1 = sS[(ty*4+1)*QT_STRIDE + ji];
            float p2 = sS[(ty*4+2)*QT_STRIDE + ji];
            float p3 = sS[(ty*4+3)*QT_STRIDE + ji];
            #pragma unroll
            for (int j = 0; j < 4; j++) {
                O[0][j] = fmaf(p0, vv[j], O[0][j]);
                O[1][j] = fmaf(p1, vv[j], O[1][j]);
                O[2][j] = fmaf(p2, vv[j], O[2][j]);
                O[3][j] = fmaf(p3, vv[j], O[3][j]);
            }
        }
    }

    // epilogue: normalize + store (b, s, h*64+d)
    #pragma unroll
    for (int i = 0; i < 4; i++) {
        float inv = 1.0f / lrow[i];
        int s = s0 + ty*4 + i;
        float4 y = make_float4(O[i][0]*inv, O[i][1]*inv, O[i][2]*inv, O[i][3]*inv);
        *(float4*)(g_att + ((size_t)b*SS + s)*DM + h*DH + tx*4) = y;
    }
}

// =========================== launch ===========================
extern "C" void kernel_launch(void* const* d_in, const int* in_sizes, int n_in,
                              void* d_out, int out_size) {
    const float* hidden = (const float*)d_in[0];
    const float* pos    = (const float*)d_in[1];
    const float* memory = (const float*)d_in[2];
    const float* Wq     = (const float*)d_in[3];
    const float* Wk     = (const float*)d_in[4];
    const float* Wv     = (const float*)d_in[5];
    const float* Wo     = (const float*)d_in[6];
    const float* gamma  = (const float*)d_in[7];
    const float* beta   = (const float*)d_in[8];
    // d_in[9] = mask: handled analytically
    float* out = (float*)d_out;

    static int smem_set = 0;
    const int flash_smem = (3*64*QT_STRIDE + 64*PT_STRIDE + 64*QT_STRIDE) * (int)sizeof(float);
    if (!smem_set) {
        cudaFuncSetAttribute(flash_kernel, cudaFuncAttributeMaxDynamicSharedMemorySize, flash_smem);
        smem_set = 1;
    }

    float *gq, *gk, *gv;
    cudaGetSymbolAddress((void**)&gq, g_q);
    cudaGetSymbolAddress((void**)&gk, g_k);
    cudaGetSymbolAddress((void**)&gv, g_v);

    ln_kernel<<<BB*KN, 256>>>(hidden, memory, gamma, beta);

    gemm_qkv_kernel<<<dim3((BB*SS)/64, HN), 256>>>(Wq, gq, SS, MEMN);
    gemm_qkv_kernel<<<dim3((BB*KN)/64, HN), 256>>>(Wk, gk, KN, 0);
    gemm_qkv_kernel<<<dim3((BB*KN)/64, HN), 256>>>(Wv, gv, KN, 0);

    flash_kernel<<<dim3(SS/64, HN, BB), 256, flash_smem>>>(pos);

    gemm_out_kernel<<<dim3((BB*SS)/64, DM/64), 256>>>(Wo, out);
}

// round 4
// speedup vs baseline: 1.3478x; 1.3478x over previous
#include <cuda_runtime.h>
#include <cuda_bf16.h>
#include <math.h>
#include <stdint.h>

#define BB    2
#define SS    2048
#define MEMN  512
#define KN    2560
#define HN    16
#define DH    64
#define DM    1024
#define LPOS  (2*KN-1)        /* 5119 */
#define SCALE_F 0.03125f      /* 1/sqrt(1024) */
#define EPSF  1e-5f
#define NEG_BIG (-1e30f)

// ------------------- device scratch (no allocation allowed) -------------------
__device__ float g_cn [BB*KN*DM];        // LN([memory; hidden])  (b, t, dm)
__device__ float g_q  [BB*HN*SS*DH];     // (b,h,s,d)
__device__ float g_k  [BB*HN*KN*DH];     // (b,h,t,d)
__device__ float g_v  [BB*HN*KN*DH];     // (b,h,t,d)
__device__ float g_att[BB*SS*DM];        // (b,s, h*64+d)
__device__ __nv_bfloat16 g_cn_h [BB*KN*DM];
__device__ __nv_bfloat16 g_cn_l [BB*KN*DM];
__device__ __nv_bfloat16 g_att_h[BB*SS*DM];
__device__ __nv_bfloat16 g_att_l[BB*SS*DM];
__device__ __nv_bfloat16 g_wt_h [4*DM*DM];   // transposed weights [n][k], hi
__device__ __nv_bfloat16 g_wt_l [4*DM*DM];   // transposed weights [n][k], lo

// ========================= helpers =========================
__device__ __forceinline__ uint32_t smem_u32(const void* p) {
    uint32_t a;
    asm("{ .reg .u64 t; cvta.to.shared.u64 t, %1; cvt.u32.u64 %0, t; }" : "=r"(a) : "l"(p));
    return a;
}
__device__ __forceinline__ void ldmatrix_x4(uint32_t* r, uint32_t addr) {
    asm volatile("ldmatrix.sync.aligned.m8n8.x4.shared.b16 {%0,%1,%2,%3}, [%4];"
        : "=r"(r[0]), "=r"(r[1]), "=r"(r[2]), "=r"(r[3]) : "r"(addr));
}
__device__ __forceinline__ void ldmatrix_x2(uint32_t* r, uint32_t addr) {
    asm volatile("ldmatrix.sync.aligned.m8n8.x2.shared.b16 {%0,%1}, [%2];"
        : "=r"(r[0]), "=r"(r[1]) : "r"(addr));
}
__device__ __forceinline__ void mma_bf16(float* d, const uint32_t* a, const uint32_t* b) {
    asm volatile(
        "mma.sync.aligned.m16n8k16.row.col.f32.bf16.bf16.f32 "
        "{%0,%1,%2,%3}, {%4,%5,%6,%7}, {%8,%9}, {%0,%1,%2,%3};"
        : "+f"(d[0]), "+f"(d[1]), "+f"(d[2]), "+f"(d[3])
        : "r"(a[0]), "r"(a[1]), "r"(a[2]), "r"(a[3]), "r"(b[0]), "r"(b[1]));
}

// =========================== LayerNorm ===========================
__global__ void __launch_bounds__(256) ln_kernel(const float* __restrict__ hidden,
                                                 const float* __restrict__ memory,
                                                 const float* __restrict__ gamma,
                                                 const float* __restrict__ beta) {
    __shared__ float red[8];
    __shared__ float s_mu, s_inv;
    const int row = blockIdx.x;                 // 0 .. B*K-1
    const int b = row / KN, t = row % KN;
    const float* src = (t < MEMN) ? (memory + ((size_t)b*MEMN + t)*DM)
                                  : (hidden + ((size_t)b*SS + (t - MEMN))*DM);
    const int tid = threadIdx.x;
    float4 x = *(const float4*)(src + tid*4);

    float s = x.x + x.y + x.z + x.w;
    #pragma unroll
    for (int o = 16; o; o >>= 1) s += __shfl_xor_sync(0xffffffffu, s, o);
    if ((tid & 31) == 0) red[tid >> 5] = s;
    __syncthreads();
    if (tid == 0) {
        float tot = 0.f;
        #pragma unroll
        for (int i = 0; i < 8; i++) tot += red[i];
        s_mu = tot * (1.0f / DM);
    }
    __syncthreads();
    const float mu = s_mu;
    float d0 = x.x - mu, d1 = x.y - mu, d2 = x.z - mu, d3 = x.w - mu;
    float vs = d0*d0 + d1*d1 + d2*d2 + d3*d3;
    #pragma unroll
    for (int o = 16; o; o >>= 1) vs += __shfl_xor_sync(0xffffffffu, vs, o);
    if ((tid & 31) == 0) red[tid >> 5] = vs;
    __syncthreads();
    if (tid == 0) {
        float tot = 0.f;
        #pragma unroll
        for (int i = 0; i < 8; i++) tot += red[i];
        s_inv = rsqrtf(tot * (1.0f / DM) + EPSF);
    }
    __syncthreads();
    const float inv = s_inv;
    float4 g = *(const float4*)(gamma + tid*4);
    float4 be = *(const float4*)(beta + tid*4);
    float4 y;
    y.x = d0 * inv * g.x + be.x;
    y.y = d1 * inv * g.y + be.y;
    y.z = d2 * inv * g.z + be.z;
    y.w = d3 * inv * g.w + be.w;
    *(float4*)(g_cn + (size_t)row*DM + tid*4) = y;
}

// ================= fp32 -> bf16 hi/lo split (activations) =================
__global__ void __launch_bounds__(256) cvt_split_kernel(const float* __restrict__ src,
                                                        __nv_bfloat16* __restrict__ dh,
                                                        __nv_bfloat16* __restrict__ dl,
                                                        int n4) {
    int i = blockIdx.x * 256 + threadIdx.x;
    if (i >= n4) return;
    float4 x = ((const float4*)src)[i];
    __nv_bfloat16 h0 = __float2bfloat16(x.x), h1 = __float2bfloat16(x.y);
    __nv_bfloat16 h2 = __float2bfloat16(x.z), h3 = __float2bfloat16(x.w);
    __nv_bfloat16 l0 = __float2bfloat16(x.x - __bfloat162float(h0));
    __nv_bfloat16 l1 = __float2bfloat16(x.y - __bfloat162float(h1));
    __nv_bfloat16 l2 = __float2bfloat16(x.z - __bfloat162float(h2));
    __nv_bfloat16 l3 = __float2bfloat16(x.w - __bfloat162float(h3));
    __nv_bfloat162* ph = (__nv_bfloat162*)(dh + 4*(size_t)i);
    __nv_bfloat162* pl = (__nv_bfloat162*)(dl + 4*(size_t)i);
    ph[0] = __halves2bfloat162(h0, h1);
    ph[1] = __halves2bfloat162(h2, h3);
    pl[0] = __halves2bfloat162(l0, l1);
    pl[1] = __halves2bfloat162(l2, l3);
}

// ======= weight transpose + split: Wt[n][k] = split(W[k][n]) =======
__global__ void __launch_bounds__(256) wt_split_kernel(const float* __restrict__ Wq,
                                                       const float* __restrict__ Wk,
                                                       const float* __restrict__ Wv,
                                                       const float* __restrict__ Wo) {
    __shared__ float t[32][33];
    const int z = blockIdx.z;
    const float* W = (z == 0) ? Wq : (z == 1) ? Wk : (z == 2) ? Wv : Wo;
    const int n0 = blockIdx.x * 32, k0 = blockIdx.y * 32;
    const int tx = threadIdx.x & 31, ty = threadIdx.x >> 5;   // 32 x 8
    #pragma unroll
    for (int r = ty; r < 32; r += 8)
        t[r][tx] = W[(size_t)(k0 + r)*DM + n0 + tx];
    __syncthreads();
    __nv_bfloat16* dh = g_wt_h + (size_t)z*DM*DM;
    __nv_bfloat16* dl = g_wt_l + (size_t)z*DM*DM;
    #pragma unroll
    for (int r = ty; r < 32; r += 8) {
        float x = t[tx][r];                       // = W[k0+tx][n0+r]
        __nv_bfloat16 h = __float2bfloat16(x);
        __nv_bfloat16 l = __float2bfloat16(x - __bfloat162float(h));
        dh[(size_t)(n0 + r)*DM + k0 + tx] = h;
        dl[(size_t)(n0 + r)*DM + k0 + tx] = l;
    }
}

// =========================== HMMA bf16x3 GEMM ===========================
// C[128x128] = A @ Wt^T, K=1024 in 16 chunks of 64. 3-term bf16 split.
// smem: 4 tiles (Ah, Al, Bh, Bl), each 128 rows x 64 bf16 = 16KB (XOR-swizzled).
#define GT_BYTES 16384
#define GSMEM    65536
__global__ void __launch_bounds__(256, 2) tc_gemm_kernel(
        const __nv_bfloat16* __restrict__ Ah, const __nv_bfloat16* __restrict__ Al,
        const __nv_bfloat16* __restrict__ Bh, const __nv_bfloat16* __restrict__ Bl,
        float* __restrict__ dst, const float* __restrict__ resid,
        int drpb, int arpb, int aoff, int mode) {
    extern __shared__ __align__(128) char smem[];
    const uint32_t sb = smem_u32(smem);
    const int tid = threadIdx.x, wid = tid >> 5, lane = tid & 31;
    const int wm = wid & 1;        // m half (64 rows)
    const int wn = wid >> 1;       // n quarter (32 cols)

    const int m0 = blockIdx.x * 128;
    const int n0 = blockIdx.y * 128;
    const int b  = m0 / drpb;
    const int rin0 = m0 % drpb;
    const long aRow0 = (long)b * arpb + aoff + rin0;

    float acc[4][4][4];
    #pragma unroll
    for (int i = 0; i < 4; i++)
        #pragma unroll
        for (int j = 0; j < 4; j++)
            #pragma unroll
            for (int e = 0; e < 4; e++) acc[i][j][e] = 0.f;

    for (int c = 0; c < 16; c++) {
        const int k0 = c * 64;
        __syncthreads();   // previous compute done before overwrite
        // fill 4 tiles: Ah, Al, Bh, Bl (128 x 64 bf16, XOR swizzle on 16B slots)
        #pragma unroll
        for (int it = 0; it < 16; it++) {
            int g  = it * 256 + tid;
            int tile = g >> 10, u = g & 1023;
            int r = u >> 3, cc = u & 7;
            const __nv_bfloat16* src;
            long row;
            if (tile < 2) { row = aRow0 + r; src = (tile == 0) ? Ah : Al; }
            else          { row = n0 + r;    src = (tile == 2) ? Bh : Bl; }
            uint4 v = *(const uint4*)(src + row * DM + k0 + cc * 8);
            *(uint4*)(smem + tile * GT_BYTES + r * 128 + (((cc ^ (r & 7))) << 4)) = v;
        }
        __syncthreads();

        #pragma unroll
        for (int ks = 0; ks < 4; ks++) {
            const int c16 = ks * 2;
            // A fragments (4 m16 tiles, hi & lo)
            uint32_t ahf[4][4], alf[4][4];
            #pragma unroll
            for (int mt = 0; mt < 4; mt++) {
                int row = wm * 64 + mt * 16 + (lane & 15);
                int cs  = (c16 + (lane >> 4)) ^ (row & 7);
                uint32_t adr = sb + row * 128 + (cs << 4);
                ldmatrix_x4(ahf[mt], adr);
                ldmatrix_x4(alf[mt], adr + GT_BYTES);
            }
            // B fragments per n8 tile, then 3 mma per (mt, nt)
            #pragma unroll
            for (int nt = 0; nt < 4; nt++) {
                int brow = wn * 32 + nt * 8 + (lane & 7);
                int cs   = (c16 + ((lane >> 3) & 1)) ^ (brow & 7);
                uint32_t badr = sb + 2 * GT_BYTES + brow * 128 + (cs << 4);
                uint32_t bhf[2], blf[2];
                ldmatrix_x2(bhf, badr);
                ldmatrix_x2(blf, badr + GT_BYTES);
                #pragma unroll
                for (int mt = 0; mt < 4; mt++) {
                    mma_bf16(acc[mt][nt], alf[mt], bhf);
                    mma_bf16(acc[mt][nt], ahf[mt], blf);
                    mma_bf16(acc[mt][nt], ahf[mt], bhf);
                }
            }
        }
    }

    // epilogue: D frag mapping — d0,d1: (row=lane/4, col=(lane%3... (lane&3)*2 +0/1); d2,d3: row+8
    #pragma unroll
    for (int mt = 0; mt < 4; mt++) {
        #pragma unroll
        for (int nt = 0; nt < 4; nt++) {
            int row0 = m0 + wm * 64 + mt * 16 + (lane >> 2);
            int n    = n0 + wn * 32 + nt * 8 + (lane & 3) * 2;
            #pragma unroll
            for (int half = 0; half < 2; half++) {
                int row = row0 + half * 8;
                float v0 = acc[mt][nt][2*half + 0];
                float v1 = acc[mt][nt][2*half + 1];
                int rin = row - b * drpb;   // row within batch (tile never crosses b)
                if (mode == 0) {
                    int h = n >> 6, d = n & 63;
                    float* dp = dst + (((size_t)(b * HN + h)) * drpb + rin) * DH + d;
                    dp[0] = v0; dp[1] = v1;
                } else {
                    float* op = dst + (size_t)row * DM + n;
                    const float* rp = resid + ((size_t)(b * KN + MEMN + rin)) * DM + n;
                    op[0] = v0 + rp[0];
                    op[1] = v1 + rp[1];
                }
            }
        }
    }
}

// =========================== Fused flash attention ===========================
#define QT_STRIDE 68
#define PT_STRIDE 132
__global__ void __launch_bounds__(256, 2) flash_kernel(const float* __restrict__ pos) {
    extern __shared__ float sm[];
    float* sQt = sm;
    float* sKt = sQt + 64*QT_STRIDE;
    float* sV  = sKt + 64*QT_STRIDE;
    float* sPt = sV  + 64*QT_STRIDE;
    float* sS  = sPt + 64*PT_STRIDE;

    const int b = blockIdx.z, h = blockIdx.y, qt = blockIdx.x;
    const int s0 = qt * 64;
    const int tid = threadIdx.x;
    const int tx = tid & 15, ty = tid >> 4;
    const int wb0 = 60 + 4*(tx - ty);

    const float* qbase = g_q + ((size_t)(b*HN + h)*SS + s0) * DH;
    const float* kbase = g_k + ((size_t)(b*HN + h)*KN) * DH;
    const float* vbase = g_v + ((size_t)(b*HN + h)*KN) * DH;
    const float* pbase = pos + (size_t)b * LPOS * DH;

    #pragma unroll
    for (int l = 0; l < 4; l++) {
        int f  = l*256 + tid;
        int r  = (f >> 2) & 63;
        int c4 = (f & 3) | ((f >> 8) << 2);
        float4 v = *(const float4*)(qbase + (size_t)r*DH + c4*4);
        sQt[(c4*4+0)*QT_STRIDE + r] = v.x;
        sQt[(c4*4+1)*QT_STRIDE + r] = v.y;
        sQt[(c4*4+2)*QT_STRIDE + r] = v.z;
        sQt[(c4*4+3)*QT_STRIDE + r] = v.w;
    }

    float mrow[4], lrow[4], O[4][4];
    #pragma unroll
    for (int i = 0; i < 4; i++) {
        mrow[i] = NEG_BIG; lrow[i] = 0.f;
        #pragma unroll
        for (int j = 0; j < 4; j++) O[i][j] = 0.f;
    }

    const int ntile = qt + 9;
    for (int jt = 0; jt < ntile; jt++) {
        const int j0 = jt * 64;
        __syncthreads();

        #pragma unroll
        for (int l = 0; l < 4; l++) {
            int f  = l*256 + tid;
            int r  = (f >> 2) & 63;
            int c4 = (f & 3) | ((f >> 8) << 2);
            float4 v = *(const float4*)(kbase + (size_t)(j0 + r)*DH + c4*4);
            sKt[(c4*4+0)*QT_STRIDE + r] = v.x;
            sKt[(c4*4+1)*QT_STRIDE + r] = v.y;
            sKt[(c4*4+2)*QT_STRIDE + r] = v.z;
            sKt[(c4*4+3)*QT_STRIDE + r] = v.w;
        }
        #pragma unroll
        for (int l = 0; l < 4; l++) {
            int f  = l*256 + tid;
            int r  = f >> 4;
            int c4 = f & 15;
            float4 v = *(const float4*)(vbase + (size_t)(j0 + r)*DH + c4*4);
            *(float4*)&sV[r*QT_STRIDE + c4*4] = v;
        }
        const int wb = 1984 + j0 - s0;
        #pragma unroll
        for (int l = 0; l < 8; l++) {
            int f  = l*256 + tid;
            int r  = (f >> 2) & 127;
            int c4 = (f & 3) | ((f >> 9) << 2);
            float4 v = *(const float4*)(pbase + (size_t)(wb + r)*DH + c4*4);
            sPt[(c4*4+0)*PT_STRIDE + r] = v.x;
            sPt[(c4*4+1)*PT_STRIDE + r] = v.y;
            sPt[(c4*4+2)*PT_STRIDE + r] = v.z;
            sPt[(c4*4+3)*PT_STRIDE + r] = v.w;
        }
        __syncthreads();

        float S[4][4] = {};
        #pragma unroll 4
        for (int d = 0; d < 64; ++d) {
            float4 q4 = *(const float4*)&sQt[d*QT_STRIDE + ty*4];
            float4 k4 = *(const float4*)&sKt[d*QT_STRIDE + tx*4];
            float4 pa = *(const float4*)&sPt[d*PT_STRIDE + wb0];
            float4 pb = *(const float4*)&sPt[d*PT_STRIDE + wb0 + 4];
            float q[4] = {q4.x, q4.y, q4.z, q4.w};
            float k[4] = {k4.x, k4.y, k4.z, k4.w};
            float p[8] = {pa.x, pa.y, pa.z, pa.w, pb.x, pb.y, pb.z, pb.w};
            #pragma unroll
            for (int i = 0; i < 4; i++)
                #pragma unroll
                for (int j = 0; j < 4; j++)
                    S[i][j] = fmaf(q[i], k[j] + p[3 + j - i], S[i][j]);
        }

        const bool lastmask = (jt == qt + 8);
        #pragma unroll
        for (int i = 0; i < 4; i++)
            #pragma unroll
            for (int j = 0; j < 4; j++) {
                float v = S[i][j] * SCALE_F;
                if (lastmask && (4*tx + j > 4*ty + i)) v = NEG_BIG;
                S[i][j] = v;
            }

        #pragma unroll
        for (int i = 0; i < 4; i++) {
            float mt = fmaxf(fmaxf(S[i][0], S[i][1]), fmaxf(S[i][2], S[i][3]));
            #pragma unroll
            for (int o = 8; o; o >>= 1) mt = fmaxf(mt, __shfl_xor_sync(0xffffffffu, mt, o));
            float mn = fmaxf(mrow[i], mt);
            float corr = __expf(mrow[i] - mn);
            mrow[i] = mn;
            float rs = 0.f;
            #pragma unroll
            for (int j = 0; j < 4; j++) {
                float p = __expf(S[i][j] - mn);
                rs += p;
                sS[(ty*4 + i)*QT_STRIDE + tx*4 + j] = p;
            }
            #pragma unroll
            for (int o = 8; o; o >>= 1) rs += __shfl_xor_sync(0xffffffffu, rs, o);
            lrow[i] = lrow[i]*corr + rs;
            #pragma unroll
            for (int j = 0; j < 4; j++) O[i][j] *= corr;
        }
        __syncthreads();

        #pragma unroll 4
        for (int ji = 0; ji < 64; ++ji) {
            float4 v4 = *(const float4*)&sV[ji*QT_STRIDE + tx*4];
            float vv[4] = {v4.x, v4.y, v4.z, v4.w};
            float p0 = sS[(ty*4+0)*QT_STRIDE + ji];
            float p1 = sS[(ty*4+1)*QT_STRIDE + ji];
            float p2 = sS[(ty*4+2)*QT_STRIDE + ji];
            float p3 = sS[(ty*4+3)*QT_STRIDE + ji];
            #pragma unroll
            for (int j = 0; j < 4; j++) {
                O[0][j] = fmaf(p0, vv[j], O[0][j]);
                O[1][j] = fmaf(p1, vv[j], O[1][j]);
                O[2][j] = fmaf(p2, vv[j], O[2][j]);
                O[3][j] = fmaf(p3, vv[j], O[3][j]);
            }
        }
    }

    #pragma unroll
    for (int i = 0; i < 4; i++) {
        float inv = 1.0f / lrow[i];
        int s = s0 + ty*4 + i;
        float4 y = make_float4(O[i][0]*inv, O[i][1]*inv, O[i][2]*inv, O[i][3]*inv);
        *(float4*)(g_att + ((size_t)b*SS + s)*DM + h*DH + tx*4) = y;
    }
}

// =========================== launch ===========================
extern "C" void kernel_launch(void* const* d_in, const int* in_sizes, int n_in,
                              void* d_out, int out_size) {
    const float* hidden = (const float*)d_in[0];
    const float* pos    = (const float*)d_in[1];
    const float* memory = (const float*)d_in[2];
    const float* Wq     = (const float*)d_in[3];
    const float* Wk     = (const float*)d_in[4];
    const float* Wv     = (const float*)d_in[5];
    const float* Wo     = (const float*)d_in[6];
    const float* gamma  = (const float*)d_in[7];
    const float* beta   = (const float*)d_in[8];
    float* out = (float*)d_out;

    static int attr_set = 0;
    const int flash_smem = (3*64*QT_STRIDE + 64*PT_STRIDE + 64*QT_STRIDE) * (int)sizeof(float);
    if (!attr_set) {
        cudaFuncSetAttribute(flash_kernel, cudaFuncAttributeMaxDynamicSharedMemorySize, flash_smem);
        cudaFuncSetAttribute(tc_gemm_kernel, cudaFuncAttributeMaxDynamicSharedMemorySize, GSMEM);
        attr_set = 1;
    }

    float *gq, *gk, *gv, *gcn, *gatt;
    __nv_bfloat16 *cnh, *cnl, *atth, *attl, *wth, *wtl;
    cudaGetSymbolAddress((void**)&gq,   g_q);
    cudaGetSymbolAddress((void**)&gk,   g_k);
    cudaGetSymbolAddress((void**)&gv,   g_v);
    cudaGetSymbolAddress((void**)&gcn,  g_cn);
    cudaGetSymbolAddress((void**)&gatt, g_att);
    cudaGetSymbolAddress((void**)&cnh,  g_cn_h);
    cudaGetSymbolAddress((void**)&cnl,  g_cn_l);
    cudaGetSymbolAddress((void**)&atth, g_att_h);
    cudaGetSymbolAddress((void**)&attl, g_att_l);
    cudaGetSymbolAddress((void**)&wth,  g_wt_h);
    cudaGetSymbolAddress((void**)&wtl,  g_wt_l);

    ln_kernel<<<BB*KN, 256>>>(hidden, memory, gamma, beta);
    cvt_split_kernel<<<(BB*KN*DM/4 + 255)/256, 256>>>(gcn, cnh, cnl, BB*KN*DM/4);
    wt_split_kernel<<<dim3(DM/32, DM/32, 4), 256>>>(Wq, Wk, Wv, Wo);

    // Q: M=4096 rows (b,s), A rows = b*KN + 512 + s
    tc_gemm_kernel<<<dim3((BB*SS)/128, DM/128), 256, GSMEM>>>(
        cnh, cnl, wth + 0*(size_t)DM*DM, wtl + 0*(size_t)DM*DM, gq, nullptr, SS, KN, MEMN, 0);
    // K: M=5120 rows (b,t)
    tc_gemm_kernel<<<dim3((BB*KN)/128, DM/128), 256, GSMEM>>>(
        cnh, cnl, wth + 1*(size_t)DM*DM, wtl + 1*(size_t)DM*DM, gk, nullptr, KN, KN, 0, 0);
    // V
    tc_gemm_kernel<<<dim3((BB*KN)/128, DM/128), 256, GSMEM>>>(
        cnh, cnl, wth + 2*(size_t)DM*DM, wtl + 2*(size_t)DM*DM, gv, nullptr, KN, KN, 0, 0);

    flash_kernel<<<dim3(SS/64, HN, BB), 256, flash_smem>>>(pos);

    cvt_split_kernel<<<(BB*SS*DM/4 + 255)/256, 256>>>(gatt, atth, attl, BB*SS*DM/4);
    // Output GEMM + residual
    tc_gemm_kernel<<<dim3((BB*SS)/128, DM/128), 256, GSMEM>>>(
        atth, attl, wth + 3*(size_t)DM*DM, wtl + 3*(size_t)DM*DM, out, gcn, SS, SS, 0, 1);
}